// round 6
// baseline (speedup 1.0000x reference)
#include <cuda_runtime.h>
#include <cstdint>
#include <cstddef>

// Problem constants
#define NU      100
#define TSTEPS  60
#define BTOT    8192
// output offsets (all float32, concatenated in reference tuple order)
static const size_t OFFU  = 0;         // u:        (B,60,7)
static const size_t OFFT  = 3440640;   // target:   (B,60)
static const size_t OFFRS = 3932160;   // respmask: (B,60)
static const size_t OFFL  = 4423680;   // licked:   (B,)
static const size_t OFFR  = 4431872;   // reward:   (B,)
static const size_t OFFZ  = 4440064;   // z_seq:    (B,60)
static const size_t OFFYF = 4931584;   // yf:       (B,100)

// noise_scale = 0.15 * sqrt(2*0.2)
#define NSCALE 0.09486832980505138f

// 8 trials per warp-PAIR (even warp: units 0..63, odd warp: 64..99).
// 8 warps/block = 4 pairs = 32 trials/block, grid = 256, 2 blocks/SM.
#define TPP 8
#define TPB 32

// ---- packed f32x2 helpers (Blackwell FFMA2) ----
__device__ __forceinline__ unsigned long long dup2(float x){
    unsigned long long r;
    asm("mov.b64 %0, {%1, %1};" : "=l"(r) : "f"(x));
    return r;
}
__device__ __forceinline__ void fma2(unsigned long long &a, unsigned long long x, unsigned long long y){
    asm("fma.rn.f32x2 %0, %1, %2, %0;" : "+l"(a) : "l"(x), "l"(y));
}
__device__ __forceinline__ float2 unpk(unsigned long long v){
    float lo, hi;
    asm("mov.b64 {%0, %1}, %2;" : "=f"(lo), "=f"(hi) : "l"(v));
    return make_float2(lo, hi);
}

// Shared layout (floats):
//   Wpk[100][128] : Wpk[j*128 + 64*h + 2*l + u] = Wrec[(32*(2h+u)+l)][j]  (0 pad)
//   Ybuf[2][100][36] : double-buffered state, col = 8*pair + s
//   WinS[7][128]  : |W_in_raw| transposed, 0 pad
//   PX[2][4][2][8]: partial-logit exchange, double-buffered
#define YS 36
#define SM_W   0
#define SM_Y   12800
#define SM_WIN 20000
#define SM_PX  20896
#define SM_FLOATS 21024

__global__ __launch_bounds__(256, 2)
void rnn_dynrouting_kernel(
    const float* __restrict__ y0,      const float* __restrict__ noise,
    const int*   __restrict__ stimI,   const int*   __restrict__ rewI,
    const int*   __restrict__ instrI,
    const float* __restrict__ WinRaw,  const float* __restrict__ Wrec,
    const float* __restrict__ brec,    const float* __restrict__ wout,
    const float* __restrict__ bout,
    float* __restrict__ out)
{
    extern __shared__ float sm[];
    float* Wpk  = sm + SM_W;
    float* Ybuf = sm + SM_Y;     // two 3600-float buffers
    float* WinS = sm + SM_WIN;
    float* PX   = sm + SM_PX;

    const int tid = threadIdx.x;

    // ---- one-time shared init ----
    for (int idx = tid; idx < 100*128; idx += 256) {
        int j = idx >> 7, c = idx & 127;
        int h = c >> 6, l = (c & 63) >> 1, u = c & 1;
        int i = 32*(2*h + u) + l;
        Wpk[idx] = (i < NU) ? Wrec[i*NU + j] : 0.0f;
    }
    for (int idx = tid; idx < 7*128; idx += 256) {
        int k = idx >> 7, i = idx & 127;
        WinS[idx] = (i < NU) ? fabsf(WinRaw[i*7 + k]) : 0.0f;
    }

    const int lane = tid & 31;
    const int warp = tid >> 5;
    const int pair = warp >> 1;
    const int half = warp & 1;
    const int tb   = blockIdx.x * TPB + pair * TPP;   // first trial of this pair
    // this warp's 2 units: iu(u) = 32*(2*half+u) + lane
    const int iu0 = 64*half + lane;
    const int iu1 = 64*half + 32 + lane;
    const bool v1 = (half == 0) || (lane < 4);        // iu1 validity (iu0 always valid)

    // publish y0 into buffer 0 (rows fully covered across the pair)
    {
        float* Y0 = Ybuf;   // buf 0
        #pragma unroll
        for (int s = 0; s < TPP; s++) {
            Y0[(size_t)iu0*YS + TPP*pair + s] = y0[(size_t)(tb + s)*NU + iu0];
            if (v1) Y0[(size_t)iu1*YS + TPP*pair + s] = y0[(size_t)(tb + s)*NU + iu1];
        }
    }
    __syncthreads();

    // per-lane constants (2 units)
    const float wo0 = wout[iu0];
    const float wo1 = v1 ? wout[iu1] : 0.0f;
    const float bdf0 = brec[iu0];
    const float bdf1 = v1 ? brec[iu1] : 0.0f;
    const float w4a = WinS[4*128 + iu0], w4b = WinS[4*128 + iu1];
    const float w5a = WinS[5*128 + iu0], w5b = WinS[5*128 + iu1];
    const float w6a = WinS[6*128 + iu0], w6b = WinS[6*128 + iu1];
    const float b0 = bout[0];

    // per-trial constants, replicated in every lane (bit-packed)
    unsigned isRewM = 0, instrBM = 0, stimP = 0;
    #pragma unroll
    for (int s = 0; s < TPP; s++) {
        int b = tb + s;
        int sv = stimI[b];
        stimP  |= (unsigned)(sv & 3) << (2*s);
        isRewM |= (unsigned)(sv == rewI[b]) << s;
        instrBM|= (unsigned)(instrI[b] > 0) << s;
    }

    // per-trial state (replicated in both warps of the pair — deterministic)
    unsigned lickedM = 0, instrFiredM = 0;
    int lickT[TPP];
    #pragma unroll
    for (int s = 0; s < TPP; s++) lickT[s] = TSTEPS + 1;

    const float* wp = Wpk + 64*half + 2*lane;
    int cur = 0;

    // ==================== time loop ====================
    for (int t = 0; t < TSTEPS; t++) {
        const bool inResp = (t >= 20) && (t < 35);
        const bool inStim = (t >= 10) && (t < 15);
        const float* Ycur = Ybuf + cur * 3600;
        float*       Ynxt = Ybuf + (cur ^ 1) * 3600;
        const float* yp = Ycur + TPP*pair;

        // ---- per-trial coefficients ----
        float cA[TPP], cB[TPP];
        unsigned instrActM = 0;
        #pragma unroll
        for (int s = 0; s < TPP; s++) {
            bool lic = (lickedM >> s) & 1;
            bool ifd = (instrFiredM >> s) & 1;
            bool irw = (isRewM >> s) & 1;
            bool ib  = (instrBM >> s) & 1;
            bool delivered = ifd || (lic && irw);
            if (ib && !delivered && (t == 30)) instrFiredM |= 1u << s;
            bool instrAct = ((instrFiredM >> s) & 1) && (t >= 30) && (t < 35);
            if (instrAct) instrActM |= 1u << s;
            bool lickDyn = lic && (t > lickT[s]) && (t < lickT[s] + 5);
            cA[s] = (instrAct ? 1.0f : 0.0f) + ((lickDyn && irw) ? 1.0f : 0.0f);
            cB[s] = lickDyn ? 1.0f : 0.0f;
        }

        // ---- prefetch noise (hidden under matvec) ----
        float nz0[TPP], nz1[TPP];
        #pragma unroll
        for (int s = 0; s < TPP; s++) {
            const float* nb = noise + (size_t)(tb + s)*(TSTEPS*NU) + (size_t)t*NU;
            nz0[s] = __ldg(nb + iu0);
            nz1[s] = v1 ? __ldg(nb + iu1) : 0.0f;
        }

        // ---- matvec: 2 units x 8 trials (4 f32x2 pairs per unit) ----
        unsigned long long acc0[4], acc1[4];
        {
            unsigned long long b0d = dup2(bdf0), b1d = dup2(bdf1);
            #pragma unroll
            for (int p = 0; p < 4; p++) { acc0[p] = b0d; acc1[p] = b1d; }
        }
        #pragma unroll 10
        for (int j = 0; j < NU; j++) {
            float2 w = *reinterpret_cast<const float2*>(wp + j*128);
            ulonglong2 ya = *reinterpret_cast<const ulonglong2*>(yp + j*YS);     // trials 0-3
            ulonglong2 yb = *reinterpret_cast<const ulonglong2*>(yp + j*YS + 4); // trials 4-7
            unsigned long long w0 = dup2(w.x), w1 = dup2(w.y);
            fma2(acc0[0], w0, ya.x); fma2(acc0[1], w0, ya.y);
            fma2(acc0[2], w0, yb.x); fma2(acc0[3], w0, yb.y);
            fma2(acc1[0], w1, ya.x); fma2(acc1[1], w1, ya.y);
            fma2(acc1[2], w1, yb.x); fma2(acc1[3], w1, yb.y);
        }

        // ---- epilogue ----
        float pre0[TPP], pre1[TPP];
        #pragma unroll
        for (int p = 0; p < 4; p++) {
            float2 a = unpk(acc0[p]); pre0[2*p] = a.x; pre0[2*p+1] = a.y;
            float2 b = unpk(acc1[p]); pre1[2*p] = b.x; pre1[2*p+1] = b.y;
        }
        if (inStim) {
            #pragma unroll
            for (int s = 0; s < TPP; s++) {
                int sv = (stimP >> (2*s)) & 3;
                pre0[s] += WinS[sv*128 + iu0];
                pre1[s] += WinS[sv*128 + iu1];   // padded rows are 0 for invalid iu1
            }
        }
        // old y from shared (conflict-free strided reads)
        float4 yoA0 = *reinterpret_cast<const float4*>(Ycur + (size_t)iu0*YS + TPP*pair);
        float4 yoA1 = *reinterpret_cast<const float4*>(Ycur + (size_t)iu0*YS + TPP*pair + 4);
        float4 yoB0, yoB1;
        if (v1) {
            yoB0 = *reinterpret_cast<const float4*>(Ycur + (size_t)iu1*YS + TPP*pair);
            yoB1 = *reinterpret_cast<const float4*>(Ycur + (size_t)iu1*YS + TPP*pair + 4);
        } else {
            yoB0 = make_float4(0.f,0.f,0.f,0.f); yoB1 = yoB0;
        }
        const float a6 = inResp ? 1.0f : 0.0f;
        const bool doAdd = (t >= 20);
        float yn0[TPP], yn1[TPP];
        #pragma unroll
        for (int s = 0; s < TPP; s++) {
            float yoa = (s<4) ? ((s==0)?yoA0.x:(s==1)?yoA0.y:(s==2)?yoA0.z:yoA0.w)
                              : ((s==4)?yoA1.x:(s==5)?yoA1.y:(s==6)?yoA1.z:yoA1.w);
            float yob = (s<4) ? ((s==0)?yoB0.x:(s==1)?yoB0.y:(s==2)?yoB0.z:yoB0.w)
                              : ((s==4)?yoB1.x:(s==5)?yoB1.y:(s==6)?yoB1.z:yoB1.w);
            float p0 = fmaf(a6, w6a, pre0[s]);
            float p1 = fmaf(a6, w6b, pre1[s]);
            if (doAdd) {
                p0 = fmaf(cA[s], w4a, fmaf(cB[s], w5a, p0));
                p1 = fmaf(cA[s], w4b, fmaf(cB[s], w5b, p1));
            }
            p0 = fmaf(NSCALE, nz0[s], p0);
            p1 = fmaf(NSCALE, nz1[s], p1);
            yn0[s] = 0.8f * yoa + 0.2f * fmaxf(p0, 0.0f);
            yn1[s] = 0.8f * yob + 0.2f * fmaxf(p1, 0.0f);
        }

        // yf on last step (from registers, coalesced within each unit)
        if (t == TSTEPS - 1) {
            #pragma unroll
            for (int s = 0; s < TPP; s++) {
                out[OFFYF + (size_t)(tb + s)*NU + iu0] = yn0[s];
                if (v1) out[OFFYF + (size_t)(tb + s)*NU + iu1] = yn1[s];
            }
        }

        // ---- publish y_new to next buffer ----
        {
            float* r0 = Ynxt + (size_t)iu0*YS + TPP*pair;
            *reinterpret_cast<float4*>(r0)     = make_float4(yn0[0], yn0[1], yn0[2], yn0[3]);
            *reinterpret_cast<float4*>(r0 + 4) = make_float4(yn0[4], yn0[5], yn0[6], yn0[7]);
            if (v1) {
                float* r1 = Ynxt + (size_t)iu1*YS + TPP*pair;
                *reinterpret_cast<float4*>(r1)     = make_float4(yn1[0], yn1[1], yn1[2], yn1[3]);
                *reinterpret_cast<float4*>(r1 + 4) = make_float4(yn1[4], yn1[5], yn1[6], yn1[7]);
            }
        }

        // ---- partial readout over this warp's units, butterfly-reduce ----
        float part[TPP];
        #pragma unroll
        for (int s = 0; s < TPP; s++)
            part[s] = fmaf(yn0[s], wo0, yn1[s] * wo1);
        #pragma unroll
        for (int off = 16; off > 0; off >>= 1) {
            #pragma unroll
            for (int s = 0; s < TPP; s++)
                part[s] += __shfl_xor_sync(0xffffffffu, part[s], off);
        }
        // lane s (<8) writes part[s] to exchange slot
        float myPart = part[0];
        #pragma unroll
        for (int s = 1; s < TPP; s++) if ((lane & 7) == s) myPart = part[s];
        float* px = PX + (t & 1)*64 + pair*16;
        if (lane < TPP) px[half*8 + lane] = myPart;

        // ---- pair barrier: orders publish + partial exchange ----
        asm volatile("bar.sync %0, %1;" :: "r"(pair + 1), "r"(64) : "memory");

        // ---- full logits (identical in both warps) ----
        float4 pe0 = *reinterpret_cast<const float4*>(px);
        float4 pe1 = *reinterpret_cast<const float4*>(px + 4);
        float4 po0 = *reinterpret_cast<const float4*>(px + 8);
        float4 po1 = *reinterpret_cast<const float4*>(px + 12);
        float lg[TPP];
        lg[0] = pe0.x + po0.x + b0; lg[1] = pe0.y + po0.y + b0;
        lg[2] = pe0.z + po0.z + b0; lg[3] = pe0.w + po0.w + b0;
        lg[4] = pe1.x + po1.x + b0; lg[5] = pe1.y + po1.y + b0;
        lg[6] = pe1.z + po1.z + b0; lg[7] = pe1.w + po1.w + b0;

        // ---- lick state machine + per-step outputs ----
        unsigned u5M = 0, u4M = 0;
        #pragma unroll
        for (int s = 0; s < TPP; s++) {
            bool lic = (lickedM >> s) & 1;
            bool trig = inResp && !lic && (lg[s] > 0.0f);  // sigmoid(x)>0.5 <=> x>0
            if (trig) { lickT[s] = t; lickedM |= 1u << s; }
            bool lic2 = (lickedM >> s) & 1;
            bool u5 = lic2 && (t >= lickT[s]) && (t < lickT[s] + 5);
            bool u4 = ((instrActM >> s) & 1) || (u5 && ((isRewM >> s) & 1));
            if (u5) u5M |= 1u << s;
            if (u4) u4M |= 1u << s;
        }
        if (half == 0 && lane < TPP) {
            int s = lane;
            float lgs = lg[0];
            #pragma unroll
            for (int q = 1; q < TPP; q++) if (s == q) lgs = lg[q];
            out[OFFZ + (size_t)(tb + s)*TSTEPS + t] = 1.0f / (1.0f + __expf(-lgs));
            size_t ub = OFFU + (size_t)(tb + s)*(TSTEPS*7) + (size_t)t*7;
            out[ub + 4] = ((u4M >> s) & 1) ? 1.0f : 0.0f;
            out[ub + 5] = ((u5M >> s) & 1) ? 1.0f : 0.0f;
        }
        cur ^= 1;
    }

    // ==================== final scalar/static outputs (even warp) ====================
    if (half == 0) {
        if (lane < TPP) {
            int s = lane;
            bool lic = (lickedM >> s) & 1;
            bool irw = (isRewM >> s) & 1;
            bool ifd = (instrFiredM >> s) & 1;
            out[OFFL + (size_t)(tb + s)] = lic ? 1.0f : 0.0f;
            out[OFFR + (size_t)(tb + s)] = (ifd || (lic && irw)) ? 1.0f : 0.0f;
        }
        for (int idx = lane; idx < TPP*TSTEPS; idx += 32) {
            int s = idx / TSTEPS;
            int t = idx - s*TSTEPS;
            size_t b = (size_t)(tb + s);
            bool resp = (t >= 20) && (t < 35);
            bool stm  = (t >= 10) && (t < 15);
            int sv = (stimP >> (2*s)) & 3;
            bool irw = (isRewM >> s) & 1;
            float* ub = out + OFFU + b*(TSTEPS*7) + (size_t)t*7;
            ub[0] = (stm && sv == 0) ? 1.0f : 0.0f;
            ub[1] = (stm && sv == 1) ? 1.0f : 0.0f;
            ub[2] = (stm && sv == 2) ? 1.0f : 0.0f;
            ub[3] = (stm && sv == 3) ? 1.0f : 0.0f;
            ub[6] = resp ? 1.0f : 0.0f;
            out[OFFT  + b*TSTEPS + t] = (irw && resp) ? 1.0f : 0.0f;
            out[OFFRS + b*TSTEPS + t] = resp ? 1.0f : 0.0f;
        }
    }
}

extern "C" void kernel_launch(void* const* d_in, const int* in_sizes, int n_in,
                              void* d_out, int out_size) {
    const float* y0     = (const float*)d_in[0];
    const float* noise  = (const float*)d_in[1];
    const int*   stim   = (const int*)  d_in[2];
    const int*   rew    = (const int*)  d_in[3];
    const int*   instr  = (const int*)  d_in[4];
    const float* WinRaw = (const float*)d_in[5];
    const float* Wrec   = (const float*)d_in[6];
    const float* brec   = (const float*)d_in[7];
    const float* wout   = (const float*)d_in[8];
    const float* bout   = (const float*)d_in[9];
    float* out = (float*)d_out;

    const int smem_bytes = SM_FLOATS * (int)sizeof(float);  // ~84.1 KB
    cudaFuncSetAttribute(rnn_dynrouting_kernel,
                         cudaFuncAttributeMaxDynamicSharedMemorySize, smem_bytes);
    rnn_dynrouting_kernel<<<BTOT/TPB, 256, smem_bytes>>>(
        y0, noise, stim, rew, instr, WinRaw, Wrec, brec, wout, bout, out);
}

// round 7
// speedup vs baseline: 1.3579x; 1.3579x over previous
#include <cuda_runtime.h>
#include <cstdint>
#include <cstddef>

// Problem constants
#define NU      100
#define TSTEPS  60
#define BTOT    8192
// output offsets (all float32, concatenated in reference tuple order)
static const size_t OFFU  = 0;         // u:        (B,60,7)
static const size_t OFFT  = 3440640;   // target:   (B,60)
static const size_t OFFRS = 3932160;   // respmask: (B,60)
static const size_t OFFL  = 4423680;   // licked:   (B,)
static const size_t OFFR  = 4431872;   // reward:   (B,)
static const size_t OFFZ  = 4440064;   // z_seq:    (B,60)
static const size_t OFFYF = 4931584;   // yf:       (B,100)

// noise_scale = 0.15 * sqrt(2*0.2)
#define NSCALE 0.09486832980505138f

// 8 trials/warp, 8 warps (256 thr)/block = 64 trials/block, grid 128.
#define TPW 8

// ---- packed f32x2 helpers (Blackwell FFMA2) ----
__device__ __forceinline__ unsigned long long dup2(float x){
    unsigned long long r;
    asm("mov.b64 %0, {%1, %1};" : "=l"(r) : "f"(x));
    return r;
}
__device__ __forceinline__ void fma2(unsigned long long &a, unsigned long long x, unsigned long long y){
    asm("fma.rn.f32x2 %0, %1, %2, %0;" : "+l"(a) : "l"(x), "l"(y));
}
__device__ __forceinline__ float2 unpk(unsigned long long v){
    float lo, hi;
    asm("mov.b64 {%0, %1}, %2;" : "=f"(lo), "=f"(hi) : "l"(v));
    return make_float2(lo, hi);
}

// Shared layout (floats):
//   Wpk[100][128] : Wpk[j*128 + 4*l + u] = Wrec[(32u+l)][j]  (0 if unit>=100)
//   Ysh [100][68] : Ysh[j*68 + col], col = 8*warp + s  (warp-private columns)
//   WinS[7][128]  : WinS[k*128 + i] = |W_in_raw[i][k]|  (0 pad)
#define YS 68
#define SM_W   0
#define SM_Y   12800
#define SM_WIN (12800 + 100*YS)
#define SM_FLOATS (12800 + 100*YS + 7*128)

__global__ __launch_bounds__(256, 1)
void rnn_dynrouting_kernel(
    const float* __restrict__ y0,      const float* __restrict__ noise,
    const int*   __restrict__ stimI,   const int*   __restrict__ rewI,
    const int*   __restrict__ instrI,
    const float* __restrict__ WinRaw,  const float* __restrict__ Wrec,
    const float* __restrict__ brec,    const float* __restrict__ wout,
    const float* __restrict__ bout,
    float* __restrict__ out)
{
    extern __shared__ float sm[];
    float* Wpk  = sm + SM_W;
    float* Ysh  = sm + SM_Y;
    float* WinS = sm + SM_WIN;

    const int tid = threadIdx.x;

    // ---- one-time shared init ----
    for (int idx = tid; idx < 100*128; idx += 256) {
        int j = idx >> 7, c = idx & 127;
        int l = c >> 2, u = c & 3;            // packed lane-major: c = 4l+u
        int i = 32*u + l;                     // unit id (interleaved ownership)
        Wpk[idx] = (i < NU) ? Wrec[i*NU + j] : 0.0f;
    }
    for (int idx = tid; idx < 7*128; idx += 256) {
        int k = idx >> 7, i = idx & 127;
        WinS[idx] = (i < NU) ? fabsf(WinRaw[i*7 + k]) : 0.0f;
    }
    __syncthreads();

    const int lane = tid & 31;
    const int warp = tid >> 5;
    const int tb   = blockIdx.x * 64 + warp * TPW;   // first trial of this warp
    // interleaved unit ownership: unit(u) = 32u + lane
    const bool v3  = (lane < 4);                     // u==3 validity

    // per-lane constants (4 units)
    float w4[4], w5[4], w6[4], wo[4];
    unsigned long long bd[4];
    #pragma unroll
    for (int u = 0; u < 4; u++) {
        int i = 32*u + lane;
        bool v = (u < 3) || v3;
        w4[u] = WinS[4*128 + i];
        w5[u] = WinS[5*128 + i];
        w6[u] = WinS[6*128 + i];
        wo[u] = v ? wout[i] : 0.0f;
        bd[u] = dup2(v ? brec[i] : 0.0f);
    }
    const float b0 = bout[0];

    // per-trial constants, replicated in every lane (bit-packed)
    unsigned isRewM = 0, instrBM = 0, stimP = 0;
    #pragma unroll
    for (int s = 0; s < TPW; s++) {
        int b = tb + s;
        int sv = stimI[b];
        stimP  |= (unsigned)(sv & 3) << (2*s);
        isRewM |= (unsigned)(sv == rewI[b]) << s;
        instrBM|= (unsigned)(instrI[b] > 0) << s;
    }

    // per-trial state (replicated)
    unsigned lickedM = 0, instrFiredM = 0;
    int lickT[TPW];
    #pragma unroll
    for (int s = 0; s < TPW; s++) lickT[s] = TSTEPS + 1;

    // y state: y[u][s]
    float y[4][TPW];
    #pragma unroll
    for (int u = 0; u < 4; u++) {
        bool v = (u < 3) || v3;
        #pragma unroll
        for (int s = 0; s < TPW; s++)
            y[u][s] = v ? y0[(size_t)(tb + s)*NU + 32*u + lane] : 0.0f;
    }
    // publish initial y (conflict-free: lane stride = 68 words = 4 banks)
    #pragma unroll
    for (int u = 0; u < 4; u++) {
        if (u < 3 || v3) {
            float* row = Ysh + (size_t)(32*u + lane)*YS + TPW*warp;
            *reinterpret_cast<float4*>(row)     = make_float4(y[u][0], y[u][1], y[u][2], y[u][3]);
            *reinterpret_cast<float4*>(row + 4) = make_float4(y[u][4], y[u][5], y[u][6], y[u][7]);
        }
    }
    __syncwarp();

    const float* wp = Wpk + 4*lane;
    const float* yp = Ysh + TPW*warp;

    // per-trial noise base pointers (advance by NU each step)
    const float* nbp[TPW];
    #pragma unroll
    for (int s = 0; s < TPW; s++)
        nbp[s] = noise + (size_t)(tb + s)*(TSTEPS*NU) + lane;

    float nz[4][TPW];

    // ==================== time loop ====================
    for (int t = 0; t < TSTEPS; t++) {
        const bool inResp = (t >= 20) && (t < 35);
        const bool inStim = (t >= 10) && (t < 15);

        // ---- per-trial coefficients (replicated in all lanes) ----
        float cA[TPW], cB[TPW];
        unsigned instrActM = 0;
        #pragma unroll
        for (int s = 0; s < TPW; s++) {
            bool lic = (lickedM >> s) & 1;
            bool ifd = (instrFiredM >> s) & 1;
            bool irw = (isRewM >> s) & 1;
            bool ib  = (instrBM >> s) & 1;
            bool delivered = ifd || (lic && irw);
            if (ib && !delivered && (t == 30)) instrFiredM |= 1u << s;
            bool instrAct = ((instrFiredM >> s) & 1) && (t >= 30) && (t < 35);
            if (instrAct) instrActM |= 1u << s;
            bool lickDyn = lic && (t > lickT[s]) && (t < lickT[s] + 5);
            cA[s] = (instrAct ? 1.0f : 0.0f) + ((lickDyn && irw) ? 1.0f : 0.0f);
            cB[s] = lickDyn ? 1.0f : 0.0f;
        }

        // ---- prefetch noise (coalesced scalars; hidden under matvec) ----
        #pragma unroll
        for (int s = 0; s < TPW; s++) {
            nz[0][s] = __ldg(nbp[s]);
            nz[1][s] = __ldg(nbp[s] + 32);
            nz[2][s] = __ldg(nbp[s] + 64);
            nz[3][s] = v3 ? __ldg(nbp[s] + 96) : 0.0f;
            nbp[s] += NU;
        }

        // ---- matvec: 4 units x 8 trials (f32x2 trial pairs) ----
        unsigned long long acc[4][4];
        #pragma unroll
        for (int u = 0; u < 4; u++) {
            acc[u][0] = bd[u]; acc[u][1] = bd[u]; acc[u][2] = bd[u]; acc[u][3] = bd[u];
        }
        #pragma unroll 10
        for (int j = 0; j < NU; j++) {
            float4 w = *reinterpret_cast<const float4*>(wp + j*128);
            ulonglong2 ya = *reinterpret_cast<const ulonglong2*>(yp + j*YS);     // trials 0-3
            ulonglong2 yb = *reinterpret_cast<const ulonglong2*>(yp + j*YS + 4); // trials 4-7
            unsigned long long w0 = dup2(w.x), w1 = dup2(w.y), w2 = dup2(w.z), w3 = dup2(w.w);
            fma2(acc[0][0], w0, ya.x); fma2(acc[0][1], w0, ya.y); fma2(acc[0][2], w0, yb.x); fma2(acc[0][3], w0, yb.y);
            fma2(acc[1][0], w1, ya.x); fma2(acc[1][1], w1, ya.y); fma2(acc[1][2], w1, yb.x); fma2(acc[1][3], w1, yb.y);
            fma2(acc[2][0], w2, ya.x); fma2(acc[2][1], w2, ya.y); fma2(acc[2][2], w2, yb.x); fma2(acc[2][3], w2, yb.y);
            fma2(acc[3][0], w3, ya.x); fma2(acc[3][1], w3, ya.y); fma2(acc[3][2], w3, yb.x); fma2(acc[3][3], w3, yb.y);
        }

        // ---- epilogue: pre -> relu -> leaky update ----
        float pre[4][TPW];
        #pragma unroll
        for (int u = 0; u < 4; u++) {
            #pragma unroll
            for (int p = 0; p < 4; p++) {
                float2 v = unpk(acc[u][p]);
                pre[u][2*p] = v.x; pre[u][2*p+1] = v.y;
            }
        }
        if (inStim) {
            #pragma unroll
            for (int s = 0; s < TPW; s++) {
                int sv = (stimP >> (2*s)) & 3;
                #pragma unroll
                for (int u = 0; u < 4; u++)
                    pre[u][s] += WinS[sv*128 + 32*u + lane];
            }
        }
        const float a6 = inResp ? 1.0f : 0.0f;
        const bool doAdd = (t >= 20);   // cA/cB only nonzero from t>=21/30
        #pragma unroll
        for (int u = 0; u < 4; u++) {
            #pragma unroll
            for (int s = 0; s < TPW; s++) {
                float p = fmaf(a6, w6[u], pre[u][s]);
                if (doAdd) p = fmaf(cA[s], w4[u], fmaf(cB[s], w5[u], p));
                p = fmaf(NSCALE, nz[u][s], p);
                float r = fmaxf(p, 0.0f);
                y[u][s] = 0.8f * y[u][s] + 0.2f * r;
            }
        }

        // ---- publish y (conflict-free) ----
        __syncwarp();   // all lanes finished reading Ysh this step
        #pragma unroll
        for (int u = 0; u < 4; u++) {
            if (u < 3 || v3) {
                float* row = Ysh + (size_t)(32*u + lane)*YS + TPW*warp;
                *reinterpret_cast<float4*>(row)     = make_float4(y[u][0], y[u][1], y[u][2], y[u][3]);
                *reinterpret_cast<float4*>(row + 4) = make_float4(y[u][4], y[u][5], y[u][6], y[u][7]);
            }
        }

        // ---- readout: logit[s] = y . w_out + b0 via shuffle butterfly ----
        float part[TPW];
        #pragma unroll
        for (int s = 0; s < TPW; s++) {
            part[s] = fmaf(y[0][s], wo[0],
                      fmaf(y[1][s], wo[1],
                      fmaf(y[2][s], wo[2], y[3][s] * wo[3])));
        }
        #pragma unroll
        for (int off = 16; off > 0; off >>= 1) {
            #pragma unroll
            for (int s = 0; s < TPW; s++)
                part[s] += __shfl_xor_sync(0xffffffffu, part[s], off);
        }

        // ---- lick state machine + per-step outputs ----
        unsigned u5M = 0, u4M = 0;
        #pragma unroll
        for (int s = 0; s < TPW; s++) {
            float lg = part[s] + b0;
            bool lic = (lickedM >> s) & 1;
            bool trig = inResp && !lic && (lg > 0.0f);   // sigmoid(x)>0.5 <=> x>0
            if (trig) { lickT[s] = t; lickedM |= 1u << s; }
            bool lic2 = (lickedM >> s) & 1;
            bool u5 = lic2 && (t >= lickT[s]) && (t < lickT[s] + 5);
            bool u4 = ((instrActM >> s) & 1) || (u5 && ((isRewM >> s) & 1));
            if (u5) u5M |= 1u << s;
            if (u4) u4M |= 1u << s;
        }
        // lane s (<8) writes trial s's z, u[...,4], u[...,5]
        float myPart = part[0];
        #pragma unroll
        for (int s = 1; s < TPW; s++) if ((lane & 7) == s) myPart = part[s];
        if (lane < TPW) {
            int s = lane;
            float lg = myPart + b0;
            out[OFFZ + (size_t)(tb + s)*TSTEPS + t] = 1.0f / (1.0f + __expf(-lg));
            size_t ub = OFFU + (size_t)(tb + s)*(TSTEPS*7) + (size_t)t*7;
            out[ub + 4] = ((u4M >> s) & 1) ? 1.0f : 0.0f;
            out[ub + 5] = ((u5M >> s) & 1) ? 1.0f : 0.0f;
        }
        __syncwarp();   // publish visible before next step's matvec reads
    }

    // ==================== final outputs ====================
    // yf (coalesced scalar stores)
    #pragma unroll
    for (int u = 0; u < 4; u++) {
        if (u < 3 || v3) {
            #pragma unroll
            for (int s = 0; s < TPW; s++)
                out[OFFYF + (size_t)(tb + s)*NU + 32*u + lane] = y[u][s];
        }
    }
    // licked / reward_delivered
    if (lane < TPW) {
        int s = lane;
        bool lic = (lickedM >> s) & 1;
        bool irw = (isRewM >> s) & 1;
        bool ifd = (instrFiredM >> s) & 1;
        out[OFFL + (size_t)(tb + s)] = lic ? 1.0f : 0.0f;
        out[OFFR + (size_t)(tb + s)] = (ifd || (lic && irw)) ? 1.0f : 0.0f;
    }
    // static per-(trial,t) outputs
    for (int idx = lane; idx < TPW*TSTEPS; idx += 32) {
        int s = idx / TSTEPS;
        int t = idx - s*TSTEPS;
        size_t b = (size_t)(tb + s);
        bool resp = (t >= 20) && (t < 35);
        bool stm  = (t >= 10) && (t < 15);
        int sv = (stimP >> (2*s)) & 3;
        bool irw = (isRewM >> s) & 1;
        float* ub = out + OFFU + b*(TSTEPS*7) + (size_t)t*7;
        ub[0] = (stm && sv == 0) ? 1.0f : 0.0f;
        ub[1] = (stm && sv == 1) ? 1.0f : 0.0f;
        ub[2] = (stm && sv == 2) ? 1.0f : 0.0f;
        ub[3] = (stm && sv == 3) ? 1.0f : 0.0f;
        ub[6] = resp ? 1.0f : 0.0f;
        out[OFFT  + b*TSTEPS + t] = (irw && resp) ? 1.0f : 0.0f;
        out[OFFRS + b*TSTEPS + t] = resp ? 1.0f : 0.0f;
    }
}

extern "C" void kernel_launch(void* const* d_in, const int* in_sizes, int n_in,
                              void* d_out, int out_size) {
    const float* y0     = (const float*)d_in[0];
    const float* noise  = (const float*)d_in[1];
    const int*   stim   = (const int*)  d_in[2];
    const int*   rew    = (const int*)  d_in[3];
    const int*   instr  = (const int*)  d_in[4];
    const float* WinRaw = (const float*)d_in[5];
    const float* Wrec   = (const float*)d_in[6];
    const float* brec   = (const float*)d_in[7];
    const float* wout   = (const float*)d_in[8];
    const float* bout   = (const float*)d_in[9];
    float* out = (float*)d_out;

    const int smem_bytes = SM_FLOATS * (int)sizeof(float);  // ~82 KB
    cudaFuncSetAttribute(rnn_dynrouting_kernel,
                         cudaFuncAttributeMaxDynamicSharedMemorySize, smem_bytes);
    rnn_dynrouting_kernel<<<BTOT/64, 256, smem_bytes>>>(
        y0, noise, stim, rew, instr, WinRaw, Wrec, brec, wout, bout, out);
}